// round 13
// baseline (speedup 1.0000x reference)
#include <cuda_runtime.h>
#include <cuda_bf16.h>
#include <cstdint>

#define FIN   128
#define FHID  64
#define NROW  1024
#define MROWS (NROW*NROW)
#define EPSV  1e-5f
#define ALPHA 0.2f
#define NEGV  -9e15f

#define GTM     256          // rows per GEMM CTA (8 warps x 32-row tiles)
#define WSTRIDE 68           // words per W-row in smem

#define GR_CTAS 512
#define GR_ROWS (MROWS/GR_CTAS)   // 2048 rows per stats CTA
#define SROWS   16
#define SSTR    136          // bf16 units per staged row (272B = 17x16B -> ldmatrix conflict-free)

// ---------------- scratch ----------------------------------------------------
__device__ float g_sum1[FIN],  g_sumsq1[FIN];
__device__ float g_bp[FHID];
__device__ float g_Wpf[FIN*FHID];              // fp32 folded W (for quad form)
__device__ __nv_bfloat16 g_WpT_hi[FHID*FIN];   // [n][k] K-major
__device__ __nv_bfloat16 g_WpT_lo[FHID*FIN];
__device__ float g_G[FIN*FIN];                 // Gram matrix X^T X
__device__ float g_sc2[FHID],  g_bi2[FHID];
__device__ float g_s3[2];
__device__ float g_eaff[2];
__device__ float g_s[MROWS];                   // 4 MB pre-BN3 scalars

// ---------------- helpers ----------------------------------------------------
__device__ __forceinline__ unsigned long long pack2(float lo, float hi) {
    unsigned long long r;
    asm("mov.b64 %0, {%1, %2};" : "=l"(r) : "f"(lo), "f"(hi));
    return r;
}
__device__ __forceinline__ float2 unpack2(unsigned long long v) {
    float2 f;
    asm("mov.b64 {%0, %1}, %2;" : "=f"(f.x), "=f"(f.y) : "l"(v));
    return f;
}
__device__ __forceinline__ unsigned long long add2(unsigned long long a,
                                                   unsigned long long b) {
    unsigned long long d;
    asm("add.rn.f32x2 %0, %1, %2;" : "=l"(d) : "l"(a), "l"(b));
    return d;
}
__device__ __forceinline__ float leakyf(float v) { return v >= 0.f ? v : ALPHA * v; }

__device__ __forceinline__ uint32_t smem_u32(const void* p) {
    uint32_t a;
    asm("{ .reg .u64 t; cvta.to.shared.u64 t, %1; cvt.u32.u64 %0, t; }" : "=r"(a) : "l"(p));
    return a;
}

// bf16x2 pack: low half <- a, high half <- b
__device__ __forceinline__ uint32_t bf16x2_of(float a, float b) {
    uint32_t d;
    asm("cvt.rn.bf16x2.f32 %0, %1, %2;" : "=r"(d) : "f"(b), "f"(a));
    return d;
}
__device__ __forceinline__ float bf16lo_f(uint32_t w) { return __uint_as_float(w << 16); }
__device__ __forceinline__ float bf16hi_f(uint32_t w) { return __uint_as_float(w & 0xFFFF0000u); }

// m16n8k16 row.col bf16 -> f32 accumulate-in-place
#define MMA16816(c, a0, a1, a2, a3, b0, b1)                                       \
    asm volatile("mma.sync.aligned.m16n8k16.row.col.f32.bf16.bf16.f32 "           \
                 "{%0,%1,%2,%3}, {%4,%5,%6,%7}, {%8,%9}, {%0,%1,%2,%3};"          \
                 : "+f"((c)[0]), "+f"((c)[1]), "+f"((c)[2]), "+f"((c)[3])         \
                 : "r"(a0), "r"(a1), "r"(a2), "r"(a3), "r"(b0), "r"(b1))

#define LDSM4T(r0, r1, r2, r3, addr)                                              \
    asm volatile("ldmatrix.sync.aligned.m8n8.x4.trans.shared.b16 "                \
                 "{%0,%1,%2,%3}, [%4];"                                           \
                 : "=r"(r0), "=r"(r1), "=r"(r2), "=r"(r3) : "r"(addr))

// ---------------- K0: zero accumulators ------------------------------------
__global__ void k_zero() {
    int t = threadIdx.x;  // 256 threads
    if (t < FIN)  { g_sum1[t] = 0.f; g_sumsq1[t] = 0.f; }
    if (t < 2)    { g_s3[t] = 0.f; }
    for (int i = t; i < FIN * FIN; i += 256) g_G[i] = 0.f;
}

// ---------------- K1: fused colstats (fp32) + Gram X^T X (bf16 tensor) ------
// 512 CTAs x 256 thr; CTA handles 2048 rows in 16-row chunks (double-buffered).
// Warp w owns Gram m-strip feats 16w..16w+15 x all 128 n-feats.
__global__ __launch_bounds__(256) void k_statsgram(const float4* __restrict__ x) {
    __shared__ __nv_bfloat16 S[2][SROWS * SSTR];
    __shared__ float shS[8 * FIN], shQ[8 * FIN];

    int tid = threadIdx.x, lane = tid & 31, wid = tid >> 5;
    int u = wid;                 // loader: rows u and u+8 of each chunk
    int c = lane;                // float4 column 0..31
    int gid = lane >> 2, tig = lane & 3;

    const float4* xb = x + (size_t)blockIdx.x * GR_ROWS * (FIN / 4);

    // ldmatrix thread->address roles (derivation in commit msg):
    // A tiles: T0 m-low/k-low, T1 m-high/k-low, T2 m-low/k-high, T3 m-high/k-high
    int rA = (lane & 16) ? 8 + (lane & 7) : (lane & 7);
    int fA = 16 * wid + ((lane & 8) ? 8 : 0);
    // B tiles: reg0 (n0,k-low), reg1 (n0,k-high), reg2 (n0+8,k-low), reg3 (n0+8,k-high)
    int rB = (lane & 8) ? 8 + (lane & 7) : (lane & 7);
    int fB = (lane & 16) ? 8 : 0;
    uint32_t aA[2], aB[2];
    aA[0] = smem_u32(&S[0][rA * SSTR + fA]);
    aA[1] = smem_u32(&S[1][rA * SSTR + fA]);
    aB[0] = smem_u32(&S[0][rB * SSTR + fB]);
    aB[1] = smem_u32(&S[1][rB * SSTR + fB]);

    float cs0 = 0.f, cs1 = 0.f, cs2 = 0.f, cs3 = 0.f;
    float cq0 = 0.f, cq1 = 0.f, cq2 = 0.f, cq3 = 0.f;
    float acc[16][4];
    #pragma unroll
    for (int nt = 0; nt < 16; nt++)
        { acc[nt][0] = 0.f; acc[nt][1] = 0.f; acc[nt][2] = 0.f; acc[nt][3] = 0.f; }

    #define LOAD_STORE_CHUNK(CH, BUF) do {                                        \
        float4 v0 = xb[((CH) * 16 + u) * 32 + c];                                 \
        float4 v1 = xb[((CH) * 16 + u + 8) * 32 + c];                             \
        cs0 += v0.x + v1.x; cq0 += v0.x * v0.x + v1.x * v1.x;                     \
        cs1 += v0.y + v1.y; cq1 += v0.y * v0.y + v1.y * v1.y;                     \
        cs2 += v0.z + v1.z; cq2 += v0.z * v0.z + v1.z * v1.z;                     \
        cs3 += v0.w + v1.w; cq3 += v0.w * v0.w + v1.w * v1.w;                     \
        *(uint2*)&S[BUF][u * SSTR + 4 * c] =                                      \
            make_uint2(bf16x2_of(v0.x, v0.y), bf16x2_of(v0.z, v0.w));             \
        *(uint2*)&S[BUF][(u + 8) * SSTR + 4 * c] =                                \
            make_uint2(bf16x2_of(v1.x, v1.y), bf16x2_of(v1.z, v1.w));             \
    } while (0)

    LOAD_STORE_CHUNK(0, 0);
    __syncthreads();

    const int NCH = GR_ROWS / 16;   // 128
    for (int ch = 0; ch < NCH; ch++) {
        int buf = ch & 1;
        if (ch + 1 < NCH) LOAD_STORE_CHUNK(ch + 1, buf ^ 1);

        uint32_t a0, a1, a2, a3;
        LDSM4T(a0, a1, a2, a3, aA[buf]);
        uint32_t bb = aB[buf];
        #pragma unroll
        for (int np = 0; np < 8; np++) {
            uint32_t b0, b1, b2, b3;
            LDSM4T(b0, b1, b2, b3, bb + np * 32);   // +16 feats = 32 bytes
            MMA16816(acc[2 * np],     a0, a1, a2, a3, b0, b1);
            MMA16816(acc[2 * np + 1], a0, a1, a2, a3, b2, b3);
        }
        __syncthreads();
    }
    #undef LOAD_STORE_CHUNK

    // colstats reduction (exact fp32)
    ((float4*)(shS + u * FIN))[c] = make_float4(cs0, cs1, cs2, cs3);
    ((float4*)(shQ + u * FIN))[c] = make_float4(cq0, cq1, cq2, cq3);
    __syncthreads();
    if (tid < FIN) {
        float a = 0.f, b = 0.f;
        #pragma unroll
        for (int ww = 0; ww < 8; ww++) { a += shS[ww * FIN + tid]; b += shQ[ww * FIN + tid]; }
        atomicAdd(&g_sum1[tid], a);
        atomicAdd(&g_sumsq1[tid], b);
    }

    // Gram accumulation into global (spread-address REDG)
    int m0 = 16 * wid + gid, m1 = m0 + 8;
    #pragma unroll
    for (int nt = 0; nt < 16; nt++) {
        int n = 8 * nt + 2 * tig;
        atomicAdd(&g_G[m0 * FIN + n],     acc[nt][0]);
        atomicAdd(&g_G[m0 * FIN + n + 1], acc[nt][1]);
        atomicAdd(&g_G[m1 * FIN + n],     acc[nt][2]);
        atomicAdd(&g_G[m1 * FIN + n + 1], acc[nt][3]);
    }
}

// ---------------- K2: fold BN1 into W; emit fp32 Wp + bf16-split W^T --------
__global__ void k_fin1(const float* __restrict__ W, const float* __restrict__ g1,
                       const float* __restrict__ b1) {
    __shared__ float s1[FIN], t1[FIN];
    int tid = threadIdx.x;  // 128 threads, tid = k
    float inv = 1.f / (float)MROWS;
    float mu  = g_sum1[tid] * inv;
    float var = g_sumsq1[tid] * inv - mu * mu;
    float rs  = rsqrtf(var + EPSV);
    float sc  = g1[tid] * rs;
    s1[tid] = sc;
    t1[tid] = b1[tid] - mu * sc;
    __syncthreads();
    float sv = s1[tid];
    for (int n = 0; n < FHID; n++) {
        float wv = sv * W[tid * FHID + n];
        g_Wpf[tid * FHID + n] = wv;
        __nv_bfloat16 bh = __float2bfloat16_rn(wv);
        float bhf = __bfloat162float(bh);
        __nv_bfloat16 bl = __float2bfloat16_rn(wv - bhf);
        g_WpT_hi[n * FIN + tid] = bh;
        g_WpT_lo[n * FIN + tid] = bl;
    }
    if (tid < FHID) {
        float acc = 0.f;
        for (int f = 0; f < FIN; f++) acc += t1[f] * W[f * FHID + tid];
        g_bp[tid] = acc;
    }
}

// ---------------- K3: BN2 affine from Gram + colsums ------------------------
// sum2[h]   = S1.Wp_h + N bp_h
// sumsq2[h] = Wp_h^T G Wp_h + 2 bp_h (S1.Wp_h) + N bp_h^2
__global__ void k_fin2g(const float* __restrict__ g2, const float* __restrict__ b2) {
    __shared__ float wcol[FIN];
    __shared__ float red[FIN], red2[FIN];
    int h = blockIdx.x, i = threadIdx.x;  // 64 blocks x 128 threads
    float wi = g_Wpf[i * FHID + h];
    wcol[i] = wi;
    __syncthreads();
    float q = 0.f;
    const float* Gi = g_G + i * FIN;
    #pragma unroll 8
    for (int j = 0; j < FIN; j++) q += Gi[j] * wcol[j];
    red[i]  = q * wi;
    red2[i] = g_sum1[i] * wi;
    __syncthreads();
    for (int off = 64; off; off >>= 1) {
        if (i < off) { red[i] += red[i + off]; red2[i] += red2[i + off]; }
        __syncthreads();
    }
    if (i == 0) {
        float bph = g_bp[h];
        float N = (float)MROWS;
        float sum2 = red2[0] + N * bph;
        float ssq2 = red[0] + 2.f * bph * red2[0] + N * bph * bph;
        float mu = sum2 / N;
        float var = ssq2 / N - mu * mu;
        float sc = g2[h] * rsqrtf(var + EPSV);
        g_sc2[h] = sc;
        g_bi2[h] = b2[h] - mu * sc;
    }
}

// ---------------- K4: GEMM + fused bn2/leaky/dot(a) epilogue ----------------
// Mainloop identical to the validated R12 kernel; epilogue consumes the
// accumulators directly: s_r = sum_h a_h * leaky(sc2_h*y_rh + bi2_h), writes
// g_s (4MB) + BN3 stats. No 256MB y scratch.
__global__ __launch_bounds__(256, 2) void k_gemm_fused(const float* __restrict__ x,
                                                       const float* __restrict__ a_vec) {
    __shared__ uint32_t sWh[FHID * WSTRIDE], sWl[FHID * WSTRIDE];
    __shared__ float sBp[FHID], sC[FHID], sD[FHID], sA[FHID];
    __shared__ float redS[8], redQ[8];

    int tid = threadIdx.x, lane = tid & 31, wid = tid >> 5;
    int gid = lane >> 2, tig = lane & 3;

    for (int i = tid; i < FHID * (FIN / 2); i += 256) {
        int n = i >> 6, w = i & 63;
        sWh[n * WSTRIDE + w] = ((const uint32_t*)g_WpT_hi)[n * (FIN / 2) + w];
        sWl[n * WSTRIDE + w] = ((const uint32_t*)g_WpT_lo)[n * (FIN / 2) + w];
    }
    if (tid < FHID) {
        sBp[tid] = g_bp[tid];
        sC[tid]  = g_sc2[tid];
        sD[tid]  = g_bi2[tid];
        sA[tid]  = a_vec[tid];
    }
    __syncthreads();

    size_t blockRow = (size_t)blockIdx.x * GTM;
    size_t row0 = blockRow + 32 * wid + gid;           // rows: row0, +8, +16, +24
    const float* xr0 = x + row0 * FIN;
    const float* xr1 = x + (row0 + 8) * FIN;
    const float* xr2 = x + (row0 + 16) * FIN;
    const float* xr3 = x + (row0 + 24) * FIN;

    float acc[2][8][4];
    #pragma unroll
    for (int m = 0; m < 2; m++)
        #pragma unroll
        for (int nt = 0; nt < 8; nt++)
            #pragma unroll
            for (int j = 0; j < 4; j++) acc[m][nt][j] = 0.f;

    #pragma unroll
    for (int kt = 0; kt < 8; kt++) {
        int k0 = 16 * kt + 4 * tig;
        float4 v0 = *(const float4*)(xr0 + k0);
        float4 v1 = *(const float4*)(xr1 + k0);
        float4 v2 = *(const float4*)(xr2 + k0);
        float4 v3 = *(const float4*)(xr3 + k0);

        uint32_t a0h = bf16x2_of(v0.x, v0.y), a2h = bf16x2_of(v0.z, v0.w);
        uint32_t a1h = bf16x2_of(v1.x, v1.y), a3h = bf16x2_of(v1.z, v1.w);
        uint32_t a4h = bf16x2_of(v2.x, v2.y), a6h = bf16x2_of(v2.z, v2.w);
        uint32_t a5h = bf16x2_of(v3.x, v3.y), a7h = bf16x2_of(v3.z, v3.w);
        uint32_t a0l = bf16x2_of(v0.x - bf16lo_f(a0h), v0.y - bf16hi_f(a0h));
        uint32_t a2l = bf16x2_of(v0.z - bf16lo_f(a2h), v0.w - bf16hi_f(a2h));
        uint32_t a1l = bf16x2_of(v1.x - bf16lo_f(a1h), v1.y - bf16hi_f(a1h));
        uint32_t a3l = bf16x2_of(v1.z - bf16lo_f(a3h), v1.w - bf16hi_f(a3h));
        uint32_t a4l = bf16x2_of(v2.x - bf16lo_f(a4h), v2.y - bf16hi_f(a4h));
        uint32_t a6l = bf16x2_of(v2.z - bf16lo_f(a6h), v2.w - bf16hi_f(a6h));
        uint32_t a5l = bf16x2_of(v3.x - bf16lo_f(a5h), v3.y - bf16hi_f(a5h));
        uint32_t a7l = bf16x2_of(v3.z - bf16lo_f(a7h), v3.w - bf16hi_f(a7h));

        const uint32_t* wh = &sWh[gid * WSTRIDE + 8 * kt + 2 * tig];
        const uint32_t* wl = &sWl[gid * WSTRIDE + 8 * kt + 2 * tig];
        #pragma unroll
        for (int nt = 0; nt < 8; nt++) {
            uint2 bh = *(const uint2*)&wh[nt * 8 * WSTRIDE];
            uint2 bl = *(const uint2*)&wl[nt * 8 * WSTRIDE];
            MMA16816(acc[0][nt], a0h, a1h, a2h, a3h, bh.x, bh.y);
            MMA16816(acc[0][nt], a0l, a1l, a2l, a3l, bh.x, bh.y);
            MMA16816(acc[0][nt], a0h, a1h, a2h, a3h, bl.x, bl.y);
            MMA16816(acc[1][nt], a4h, a5h, a6h, a7h, bh.x, bh.y);
            MMA16816(acc[1][nt], a4l, a5l, a6l, a7l, bh.x, bh.y);
            MMA16816(acc[1][nt], a4h, a5h, a6h, a7h, bl.x, bl.y);
        }
    }

    // ---- fused epilogue: bn2 + leaky + dot(a) ------------------------------
    float p0 = 0.f, p1 = 0.f, p2 = 0.f, p3 = 0.f;   // rows row0, +8, +16, +24
    #pragma unroll
    for (int nt = 0; nt < 8; nt++) {
        int col = 8 * nt + 2 * tig;
        float bp0 = sBp[col],  bp1 = sBp[col + 1];
        float C0 = sC[col], D0 = sD[col], A0 = sA[col];
        float C1 = sC[col + 1], D1 = sD[col + 1], A1 = sA[col + 1];
        p0 += A0 * leakyf((acc[0][nt][0] + bp0) * C0 + D0)
            + A1 * leakyf((acc[0][nt][1] + bp1) * C1 + D1);
        p1 += A0 * leakyf((acc[0][nt][2] + bp0) * C0 + D0)
            + A1 * leakyf((acc[0][nt][3] + bp1) * C1 + D1);
        p2 += A0 * leakyf((acc[1][nt][0] + bp0) * C0 + D0)
            + A1 * leakyf((acc[1][nt][1] + bp1) * C1 + D1);
        p3 += A0 * leakyf((acc[1][nt][2] + bp0) * C0 + D0)
            + A1 * leakyf((acc[1][nt][3] + bp1) * C1 + D1);
    }
    unsigned long long t0 = pack2(p0, p1), t1 = pack2(p2, p3);
    t0 = add2(t0, __shfl_xor_sync(0xffffffffu, t0, 1));
    t0 = add2(t0, __shfl_xor_sync(0xffffffffu, t0, 2));
    t1 = add2(t1, __shfl_xor_sync(0xffffffffu, t1, 1));
    t1 = add2(t1, __shfl_xor_sync(0xffffffffu, t1, 2));

    float ps = 0.f, pq = 0.f;
    if (tig == 0) {
        float2 s0 = unpack2(t0), s1 = unpack2(t1);
        size_t base = blockRow + 32 * wid + gid;
        g_s[base]      = s0.x;
        g_s[base + 8]  = s0.y;
        g_s[base + 16] = s1.x;
        g_s[base + 24] = s1.y;
        ps = s0.x + s0.y + s1.x + s1.y;
        pq = s0.x * s0.x + s0.y * s0.y + s1.x * s1.x + s1.y * s1.y;
    }
    #pragma unroll
    for (int o = 16; o; o >>= 1) {
        ps += __shfl_xor_sync(0xffffffffu, ps, o);
        pq += __shfl_xor_sync(0xffffffffu, pq, o);
    }
    if (lane == 0) { redS[wid] = ps; redQ[wid] = pq; }
    __syncthreads();
    if (tid == 0) {
        float S = 0.f, Q = 0.f;
        #pragma unroll
        for (int i = 0; i < 8; i++) { S += redS[i]; Q += redQ[i]; }
        atomicAdd(&g_s3[0], S);
        atomicAdd(&g_s3[1], Q);
    }
}

// ---------------- K5: finalize BN3 affine ----------------------------------
__global__ void k_fin3(const float* __restrict__ g3, const float* __restrict__ b3) {
    float inv = 1.f / (float)MROWS;
    float mu  = g_s3[0] * inv;
    float var = g_s3[1] * inv - mu * mu;
    float rs  = rsqrtf(var + EPSV);
    float c   = g3[0] * rs;
    g_eaff[0] = c;
    g_eaff[1] = b3[0] - mu * c;
}

// ---------------- K6: masked row softmax ------------------------------------
__global__ void k_softmax(const float* __restrict__ adj_mean, float* __restrict__ out) {
    __shared__ float redm[8], reds[8];
    int row = blockIdx.x, tid = threadIdx.x, lane = tid & 31, w = tid >> 5;
    float c3 = g_eaff[0], d3 = g_eaff[1];
    float4 sv = ((const float4*)(g_s + (size_t)row * NROW))[tid];
    float4 mv = ((const float4*)(adj_mean + (size_t)row * NROW))[tid];
    float v0 = (mv.x > 0.f) ? leakyf(sv.x * c3 + d3) : NEGV;
    float v1 = (mv.y > 0.f) ? leakyf(sv.y * c3 + d3) : NEGV;
    float v2 = (mv.z > 0.f) ? leakyf(sv.z * c3 + d3) : NEGV;
    float v3 = (mv.w > 0.f) ? leakyf(sv.w * c3 + d3) : NEGV;

    float m = fmaxf(fmaxf(v0, v1), fmaxf(v2, v3));
    #pragma unroll
    for (int o = 16; o; o >>= 1) m = fmaxf(m, __shfl_xor_sync(0xffffffffu, m, o));
    if (lane == 0) redm[w] = m;
    __syncthreads();
    if (tid < 8) {
        float t = redm[tid];
        #pragma unroll
        for (int o = 4; o; o >>= 1) t = fmaxf(t, __shfl_xor_sync(0xffu, t, o));
        if (tid == 0) redm[0] = t;
    }
    __syncthreads();
    float rm = redm[0];

    float p0 = expf(v0 - rm), p1 = expf(v1 - rm), p2 = expf(v2 - rm), p3 = expf(v3 - rm);
    float s = p0 + p1 + p2 + p3;
    #pragma unroll
    for (int o = 16; o; o >>= 1) s += __shfl_xor_sync(0xffffffffu, s, o);
    if (lane == 0) reds[w] = s;
    __syncthreads();
    if (tid < 8) {
        float t = reds[tid];
        #pragma unroll
        for (int o = 4; o; o >>= 1) t += __shfl_xor_sync(0xffu, t, o);
        if (tid == 0) reds[0] = t;
    }
    __syncthreads();
    float invs = 1.f / reds[0];

    ((float4*)(out + (size_t)row * NROW))[tid] =
        make_float4(p0 * invs, p1 * invs, p2 * invs, p3 * invs);
}

// ---------------- launcher ---------------------------------------------------
extern "C" void kernel_launch(void* const* d_in, const int* in_sizes, int n_in,
                              void* d_out, int out_size) {
    const float* adj      = (const float*)d_in[0];
    const float* adj_mean = (const float*)d_in[1];
    const float* W        = (const float*)d_in[2];
    const float* a        = (const float*)d_in[3];
    const float* gamma1   = (const float*)d_in[4];
    const float* beta1    = (const float*)d_in[5];
    const float* gamma2   = (const float*)d_in[6];
    const float* beta2    = (const float*)d_in[7];
    const float* gamma3   = (const float*)d_in[8];
    const float* beta3    = (const float*)d_in[9];
    float* out            = (float*)d_out;

    k_zero<<<1, 256>>>();
    k_statsgram<<<GR_CTAS, 256>>>((const float4*)adj);
    k_fin1<<<1, 128>>>(W, gamma1, beta1);
    k_fin2g<<<FHID, 128>>>(gamma2, beta2);
    k_gemm_fused<<<MROWS / GTM, 256>>>(adj, a);
    k_fin3<<<1, 1>>>(gamma3, beta3);
    k_softmax<<<NROW, 256>>>(adj_mean, out);
}

// round 14
// speedup vs baseline: 1.1391x; 1.1391x over previous
#include <cuda_runtime.h>
#include <cuda_bf16.h>
#include <cstdint>

#define FIN   128
#define FHID  64
#define NROW  1024
#define MROWS (NROW*NROW)
#define EPSV  1e-5f
#define ALPHA 0.2f
#define NEGV  -9e15f

#define GTM     256          // rows per GEMM CTA (8 warps x 32-row tiles)
#define WSTRIDE 68           // words per W-row in smem

#define GR_CTAS 512
#define GR_ROWS (MROWS/GR_CTAS)   // 2048 rows per stats CTA
#define CROWS   32                // rows per pipeline chunk (2 k-steps)
#define NITER   (GR_ROWS/CROWS)   // 64
#define SSTR    136               // bf16 per staged row (272B -> ldmatrix conflict-free)

// ---------------- scratch ----------------------------------------------------
__device__ float g_sum1[FIN],  g_sumsq1[FIN];
__device__ float g_bp[FHID];
__device__ float g_Wpf[FIN*FHID];              // fp32 folded W (for quad form)
__device__ __nv_bfloat16 g_WpT_hi[FHID*FIN];   // [n][k] K-major
__device__ __nv_bfloat16 g_WpT_lo[FHID*FIN];
__device__ float g_Gpart[(size_t)GR_CTAS*FIN*FIN];  // 32 MB per-CTA Gram partials
__device__ float g_G[FIN*FIN];                 // reduced Gram X^T X
__device__ float g_sc2[FHID],  g_bi2[FHID];
__device__ float g_s3[2];
__device__ float g_eaff[2];
__device__ float g_s[MROWS];                   // 4 MB pre-BN3 scalars

// ---------------- helpers ----------------------------------------------------
__device__ __forceinline__ unsigned long long pack2(float lo, float hi) {
    unsigned long long r;
    asm("mov.b64 %0, {%1, %2};" : "=l"(r) : "f"(lo), "f"(hi));
    return r;
}
__device__ __forceinline__ float2 unpack2(unsigned long long v) {
    float2 f;
    asm("mov.b64 {%0, %1}, %2;" : "=f"(f.x), "=f"(f.y) : "l"(v));
    return f;
}
__device__ __forceinline__ unsigned long long add2(unsigned long long a,
                                                   unsigned long long b) {
    unsigned long long d;
    asm("add.rn.f32x2 %0, %1, %2;" : "=l"(d) : "l"(a), "l"(b));
    return d;
}
__device__ __forceinline__ float leakyf(float v) { return v >= 0.f ? v : ALPHA * v; }

__device__ __forceinline__ uint32_t smem_u32(const void* p) {
    uint32_t a;
    asm("{ .reg .u64 t; cvta.to.shared.u64 t, %1; cvt.u32.u64 %0, t; }" : "=r"(a) : "l"(p));
    return a;
}

// bf16x2 pack: low half <- a, high half <- b
__device__ __forceinline__ uint32_t bf16x2_of(float a, float b) {
    uint32_t d;
    asm("cvt.rn.bf16x2.f32 %0, %1, %2;" : "=r"(d) : "f"(b), "f"(a));
    return d;
}
__device__ __forceinline__ float bf16lo_f(uint32_t w) { return __uint_as_float(w << 16); }
__device__ __forceinline__ float bf16hi_f(uint32_t w) { return __uint_as_float(w & 0xFFFF0000u); }

// m16n8k16 row.col bf16 -> f32 accumulate-in-place
#define MMA16816(c, a0, a1, a2, a3, b0, b1)                                       \
    asm volatile("mma.sync.aligned.m16n8k16.row.col.f32.bf16.bf16.f32 "           \
                 "{%0,%1,%2,%3}, {%4,%5,%6,%7}, {%8,%9}, {%0,%1,%2,%3};"          \
                 : "+f"((c)[0]), "+f"((c)[1]), "+f"((c)[2]), "+f"((c)[3])         \
                 : "r"(a0), "r"(a1), "r"(a2), "r"(a3), "r"(b0), "r"(b1))

#define LDSM4T(r0, r1, r2, r3, addr)                                              \
    asm volatile("ldmatrix.sync.aligned.m8n8.x4.trans.shared.b16 "                \
                 "{%0,%1,%2,%3}, [%4];"                                           \
                 : "=r"(r0), "=r"(r1), "=r"(r2), "=r"(r3) : "r"(addr))

// ---------------- K0: zero accumulators ------------------------------------
__global__ void k_zero() {
    int t = threadIdx.x;  // 256 threads
    if (t < FIN)  { g_sum1[t] = 0.f; g_sumsq1[t] = 0.f; }
    if (t < 2)    { g_s3[t] = 0.f; }
    for (int i = t; i < FIN * FIN; i += 256) g_G[i] = 0.f;
}

// ---------------- K1: fused colstats (fp32) + Gram X^T X (bf16 tensor) ------
// 512 CTAs x 256 thr; 2048 rows per CTA in 32-row double-buffered chunks.
// Fragment mapping identical to the R13-validated version; Gram partials go to
// g_Gpart via coalesced STG (no atomics).
__global__ __launch_bounds__(256) void k_statsgram(const float4* __restrict__ x) {
    __shared__ __nv_bfloat16 S[2][CROWS * SSTR];
    __shared__ float shS[8 * FIN], shQ[8 * FIN];

    int tid = threadIdx.x, lane = tid & 31, wid = tid >> 5;
    int gid = lane >> 2, tig = lane & 3;

    const float4* xb = x + (size_t)blockIdx.x * GR_ROWS * (FIN / 4);

    // ldmatrix thread->address roles (validated R13 mapping)
    int rA = (lane & 16) ? 8 + (lane & 7) : (lane & 7);
    int fA = 16 * wid + ((lane & 8) ? 8 : 0);
    int rB = (lane & 8) ? 8 + (lane & 7) : (lane & 7);
    int fB = (lane & 16) ? 8 : 0;
    uint32_t aA[2], aB[2];
    aA[0] = smem_u32(&S[0][rA * SSTR + fA]);
    aA[1] = smem_u32(&S[1][rA * SSTR + fA]);
    aB[0] = smem_u32(&S[0][rB * SSTR + fB]);
    aB[1] = smem_u32(&S[1][rB * SSTR + fB]);
    const uint32_t KOFF = 16 * SSTR * 2;   // bytes: second k-step (+16 rows)

    float4 cs = make_float4(0.f, 0.f, 0.f, 0.f);
    float4 cq = make_float4(0.f, 0.f, 0.f, 0.f);
    float acc[16][4];
    #pragma unroll
    for (int nt = 0; nt < 16; nt++)
        { acc[nt][0] = 0.f; acc[nt][1] = 0.f; acc[nt][2] = 0.f; acc[nt][3] = 0.f; }

    float4 v0, v1, v2, v3;   // staged rows wid, +8, +16, +24 of a chunk

    #define LOADC(CH) do {                                                        \
        int rb = (CH) * CROWS;                                                    \
        v0 = xb[(rb + wid) * 32 + lane];                                          \
        v1 = xb[(rb + wid + 8) * 32 + lane];                                      \
        v2 = xb[(rb + wid + 16) * 32 + lane];                                     \
        v3 = xb[(rb + wid + 24) * 32 + lane];                                     \
        cs.x += v0.x + v1.x + v2.x + v3.x;                                        \
        cs.y += v0.y + v1.y + v2.y + v3.y;                                        \
        cs.z += v0.z + v1.z + v2.z + v3.z;                                        \
        cs.w += v0.w + v1.w + v2.w + v3.w;                                        \
        cq.x += v0.x * v0.x + v1.x * v1.x + v2.x * v2.x + v3.x * v3.x;            \
        cq.y += v0.y * v0.y + v1.y * v1.y + v2.y * v2.y + v3.y * v3.y;            \
        cq.z += v0.z * v0.z + v1.z * v1.z + v2.z * v2.z + v3.z * v3.z;            \
        cq.w += v0.w * v0.w + v1.w * v1.w + v2.w * v2.w + v3.w * v3.w;            \
    } while (0)

    #define STSC(BUF) do {                                                        \
        *(uint2*)&S[BUF][wid * SSTR + 4 * lane] =                                 \
            make_uint2(bf16x2_of(v0.x, v0.y), bf16x2_of(v0.z, v0.w));             \
        *(uint2*)&S[BUF][(wid + 8) * SSTR + 4 * lane] =                           \
            make_uint2(bf16x2_of(v1.x, v1.y), bf16x2_of(v1.z, v1.w));             \
        *(uint2*)&S[BUF][(wid + 16) * SSTR + 4 * lane] =                          \
            make_uint2(bf16x2_of(v2.x, v2.y), bf16x2_of(v2.z, v2.w));             \
        *(uint2*)&S[BUF][(wid + 24) * SSTR + 4 * lane] =                          \
            make_uint2(bf16x2_of(v3.x, v3.y), bf16x2_of(v3.z, v3.w));             \
    } while (0)

    // prologue: chunk0 staged, chunk1 in regs
    LOADC(0);
    STSC(0);
    __syncthreads();
    LOADC(1);

    #pragma unroll 1
    for (int it = 0; it < NITER; it++) {
        int buf = it & 1;
        if (it + 1 < NITER) STSC(buf ^ 1);
        __syncthreads();
        if (it + 2 < NITER) LOADC(it + 2);
        // compute chunk it: 2 k-steps
        #pragma unroll
        for (int ks = 0; ks < 2; ks++) {
            uint32_t off = ks ? KOFF : 0;
            uint32_t a0, a1, a2, a3;
            LDSM4T(a0, a1, a2, a3, aA[buf] + off);
            uint32_t bb = aB[buf] + off;
            #pragma unroll
            for (int np = 0; np < 8; np++) {
                uint32_t b0, b1, b2, b3;
                LDSM4T(b0, b1, b2, b3, bb + np * 32);
                MMA16816(acc[2 * np],     a0, a1, a2, a3, b0, b1);
                MMA16816(acc[2 * np + 1], a0, a1, a2, a3, b2, b3);
            }
        }
        __syncthreads();
    }
    #undef LOADC
    #undef STSC

    // colstats reduction (exact fp32)
    ((float4*)(shS + wid * FIN))[lane] = cs;
    ((float4*)(shQ + wid * FIN))[lane] = cq;
    __syncthreads();
    if (tid < FIN) {
        float a = 0.f, b = 0.f;
        #pragma unroll
        for (int ww = 0; ww < 8; ww++) { a += shS[ww * FIN + tid]; b += shQ[ww * FIN + tid]; }
        atomicAdd(&g_sum1[tid], a);
        atomicAdd(&g_sumsq1[tid], b);
    }

    // Gram partial store (coalesced float2 STG, no atomics)
    float* P = g_Gpart + (size_t)blockIdx.x * FIN * FIN;
    int m0 = 16 * wid + gid, m1 = m0 + 8;
    #pragma unroll
    for (int nt = 0; nt < 16; nt++) {
        int n = 8 * nt + 2 * tig;
        *(float2*)&P[m0 * FIN + n] = make_float2(acc[nt][0], acc[nt][1]);
        *(float2*)&P[m1 * FIN + n] = make_float2(acc[nt][2], acc[nt][3]);
    }
}

// ---------------- K2: reduce Gram partials ----------------------------------
// 128 blocks (4 c-slices x 32 o-slices) x 256 thr. Coalesced along n.
__global__ void k_gred() {
    __shared__ float4 sh[128];
    int os = blockIdx.x & 31, cslice = blockIdx.x >> 5;
    int col = os * 128 + (threadIdx.x & 127);    // float4 column 0..4095
    int rg  = threadIdx.x >> 7;                  // 0..1
    const float4* p = (const float4*)g_Gpart;

    float4 a0 = make_float4(0,0,0,0), a1 = a0, a2 = a0, a3 = a0;
    int c0 = cslice * 128 + rg;
    #pragma unroll 1
    for (int k = 0; k < 64; k += 4) {
        float4 u0 = p[(size_t)(c0 + 2 * (k + 0)) * 4096 + col];
        float4 u1 = p[(size_t)(c0 + 2 * (k + 1)) * 4096 + col];
        float4 u2 = p[(size_t)(c0 + 2 * (k + 2)) * 4096 + col];
        float4 u3 = p[(size_t)(c0 + 2 * (k + 3)) * 4096 + col];
        a0.x += u0.x; a0.y += u0.y; a0.z += u0.z; a0.w += u0.w;
        a1.x += u1.x; a1.y += u1.y; a1.z += u1.z; a1.w += u1.w;
        a2.x += u2.x; a2.y += u2.y; a2.z += u2.z; a2.w += u2.w;
        a3.x += u3.x; a3.y += u3.y; a3.z += u3.z; a3.w += u3.w;
    }
    float4 s;
    s.x = a0.x + a1.x + a2.x + a3.x;
    s.y = a0.y + a1.y + a2.y + a3.y;
    s.z = a0.z + a1.z + a2.z + a3.z;
    s.w = a0.w + a1.w + a2.w + a3.w;

    if (rg == 1) sh[threadIdx.x & 127] = s;
    __syncthreads();
    if (rg == 0) {
        float4 t = sh[threadIdx.x & 127];
        float* G = g_G + (size_t)col * 4;
        atomicAdd(&G[0], s.x + t.x);
        atomicAdd(&G[1], s.y + t.y);
        atomicAdd(&G[2], s.z + t.z);
        atomicAdd(&G[3], s.w + t.w);
    }
}

// ---------------- K3: fold BN1 into W; emit fp32 Wp + bf16-split W^T --------
__global__ void k_fin1(const float* __restrict__ W, const float* __restrict__ g1,
                       const float* __restrict__ b1) {
    __shared__ float s1[FIN], t1[FIN];
    int tid = threadIdx.x;  // 128 threads, tid = k
    float inv = 1.f / (float)MROWS;
    float mu  = g_sum1[tid] * inv;
    float var = g_sumsq1[tid] * inv - mu * mu;
    float rs  = rsqrtf(var + EPSV);
    float sc  = g1[tid] * rs;
    s1[tid] = sc;
    t1[tid] = b1[tid] - mu * sc;
    __syncthreads();
    float sv = s1[tid];
    for (int n = 0; n < FHID; n++) {
        float wv = sv * W[tid * FHID + n];
        g_Wpf[tid * FHID + n] = wv;
        __nv_bfloat16 bh = __float2bfloat16_rn(wv);
        float bhf = __bfloat162float(bh);
        __nv_bfloat16 bl = __float2bfloat16_rn(wv - bhf);
        g_WpT_hi[n * FIN + tid] = bh;
        g_WpT_lo[n * FIN + tid] = bl;
    }
    if (tid < FHID) {
        float acc = 0.f;
        for (int f = 0; f < FIN; f++) acc += t1[f] * W[f * FHID + tid];
        g_bp[tid] = acc;
    }
}

// ---------------- K4: BN2 affine from Gram + colsums (coalesced) ------------
// q_h = sum_j w_j * (sum_i G_ij w_i); inner accumulation coalesced over tid=j.
__global__ void k_fin2g(const float* __restrict__ g2, const float* __restrict__ b2) {
    __shared__ float wcol[FIN];
    __shared__ float rq[FIN], rs2[FIN];
    int h = blockIdx.x, tid = threadIdx.x;  // 64 blocks x 128 threads
    wcol[tid] = g_Wpf[tid * FHID + h];
    __syncthreads();
    float ca = 0.f;
    #pragma unroll 8
    for (int i = 0; i < FIN; i++) ca += g_G[i * FIN + tid] * wcol[i];
    rq[tid]  = ca * wcol[tid];
    rs2[tid] = g_sum1[tid] * wcol[tid];
    __syncthreads();
    for (int off = 64; off; off >>= 1) {
        if (tid < off) { rq[tid] += rq[tid + off]; rs2[tid] += rs2[tid + off]; }
        __syncthreads();
    }
    if (tid == 0) {
        float bph = g_bp[h];
        float N = (float)MROWS;
        float sum2 = rs2[0] + N * bph;
        float ssq2 = rq[0] + 2.f * bph * rs2[0] + N * bph * bph;
        float mu = sum2 / N;
        float var = ssq2 / N - mu * mu;
        float sc = g2[h] * rsqrtf(var + EPSV);
        g_sc2[h] = sc;
        g_bi2[h] = b2[h] - mu * sc;
    }
}

// ---------------- K5: GEMM + fused bn2/leaky/dot(a) epilogue ----------------
__global__ __launch_bounds__(256, 2) void k_gemm_fused(const float* __restrict__ x,
                                                       const float* __restrict__ a_vec) {
    __shared__ uint32_t sWh[FHID * WSTRIDE], sWl[FHID * WSTRIDE];
    __shared__ float sBp[FHID], sC[FHID], sD[FHID], sA[FHID];
    __shared__ float redS[8], redQ[8];

    int tid = threadIdx.x, lane = tid & 31, wid = tid >> 5;
    int gid = lane >> 2, tig = lane & 3;

    for (int i = tid; i < FHID * (FIN / 2); i += 256) {
        int n = i >> 6, w = i & 63;
        sWh[n * WSTRIDE + w] = ((const uint32_t*)g_WpT_hi)[n * (FIN / 2) + w];
        sWl[n * WSTRIDE + w] = ((const uint32_t*)g_WpT_lo)[n * (FIN / 2) + w];
    }
    if (tid < FHID) {
        sBp[tid] = g_bp[tid];
        sC[tid]  = g_sc2[tid];
        sD[tid]  = g_bi2[tid];
        sA[tid]  = a_vec[tid];
    }
    __syncthreads();

    size_t blockRow = (size_t)blockIdx.x * GTM;
    size_t row0 = blockRow + 32 * wid + gid;
    const float* xr0 = x + row0 * FIN;
    const float* xr1 = x + (row0 + 8) * FIN;
    const float* xr2 = x + (row0 + 16) * FIN;
    const float* xr3 = x + (row0 + 24) * FIN;

    float acc[2][8][4];
    #pragma unroll
    for (int m = 0; m < 2; m++)
        #pragma unroll
        for (int nt = 0; nt < 8; nt++)
            #pragma unroll
            for (int j = 0; j < 4; j++) acc[m][nt][j] = 0.f;

    #pragma unroll
    for (int kt = 0; kt < 8; kt++) {
        int k0 = 16 * kt + 4 * tig;
        float4 v0 = *(const float4*)(xr0 + k0);
        float4 v1 = *(const float4*)(xr1 + k0);
        float4 v2 = *(const float4*)(xr2 + k0);
        float4 v3 = *(const float4*)(xr3 + k0);

        uint32_t a0h = bf16x2_of(v0.x, v0.y), a2h = bf16x2_of(v0.z, v0.w);
        uint32_t a1h = bf16x2_of(v1.x, v1.y), a3h = bf16x2_of(v1.z, v1.w);
        uint32_t a4h = bf16x2_of(v2.x, v2.y), a6h = bf16x2_of(v2.z, v2.w);
        uint32_t a5h = bf16x2_of(v3.x, v3.y), a7h = bf16x2_of(v3.z, v3.w);
        uint32_t a0l = bf16x2_of(v0.x - bf16lo_f(a0h), v0.y - bf16hi_f(a0h));
        uint32_t a2l = bf16x2_of(v0.z - bf16lo_f(a2h), v0.w - bf16hi_f(a2h));
        uint32_t a1l = bf16x2_of(v1.x - bf16lo_f(a1h), v1.y - bf16hi_f(a1h));
        uint32_t a3l = bf16x2_of(v1.z - bf16lo_f(a3h), v1.w - bf16hi_f(a3h));
        uint32_t a4l = bf16x2_of(v2.x - bf16lo_f(a4h), v2.y - bf16hi_f(a4h));
        uint32_t a6l = bf16x2_of(v2.z - bf16lo_f(a6h), v2.w - bf16hi_f(a6h));
        uint32_t a5l = bf16x2_of(v3.x - bf16lo_f(a5h), v3.y - bf16hi_f(a5h));
        uint32_t a7l = bf16x2_of(v3.z - bf16lo_f(a7h), v3.w - bf16hi_f(a7h));

        const uint32_t* wh = &sWh[gid * WSTRIDE + 8 * kt + 2 * tig];
        const uint32_t* wl = &sWl[gid * WSTRIDE + 8 * kt + 2 * tig];
        #pragma unroll
        for (int nt = 0; nt < 8; nt++) {
            uint2 bh = *(const uint2*)&wh[nt * 8 * WSTRIDE];
            uint2 bl = *(const uint2*)&wl[nt * 8 * WSTRIDE];
            MMA16816(acc[0][nt], a0h, a1h, a2h, a3h, bh.x, bh.y);
            MMA16816(acc[0][nt], a0l, a1l, a2l, a3l, bh.x, bh.y);
            MMA16816(acc[0][nt], a0h, a1h, a2h, a3h, bl.x, bl.y);
            MMA16816(acc[1][nt], a4h, a5h, a6h, a7h, bh.x, bh.y);
            MMA16816(acc[1][nt], a4l, a5l, a6l, a7l, bh.x, bh.y);
            MMA16816(acc[1][nt], a4h, a5h, a6h, a7h, bl.x, bl.y);
        }
    }

    float p0 = 0.f, p1 = 0.f, p2 = 0.f, p3 = 0.f;
    #pragma unroll
    for (int nt = 0; nt < 8; nt++) {
        int col = 8 * nt + 2 * tig;
        float bp0 = sBp[col],  bp1 = sBp[col + 1];
        float C0 = sC[col], D0 = sD[col], A0 = sA[col];
        float C1 = sC[col + 1], D1 = sD[col + 1], A1 = sA[col + 1];
        p0 += A0 * leakyf((acc[0][nt][0] + bp0) * C0 + D0)
            + A1 * leakyf((acc[0][nt][1] + bp1) * C1 + D1);
        p1 += A0 * leakyf((acc[0][nt][2] + bp0) * C0 + D0)
            + A1 * leakyf((acc[0][nt][3] + bp1) * C1 + D1);
        p2 += A0 * leakyf((acc[1][nt][0] + bp0) * C0 + D0)
            + A1 * leakyf((acc[1][nt][1] + bp1) * C1 + D1);
        p3 += A0 * leakyf((acc[1][nt][2] + bp0) * C0 + D0)
            + A1 * leakyf((acc[1][nt][3] + bp1) * C1 + D1);
    }
    unsigned long long t0 = pack2(p0, p1), t1 = pack2(p2, p3);
    t0 = add2(t0, __shfl_xor_sync(0xffffffffu, t0, 1));
    t0 = add2(t0, __shfl_xor_sync(0xffffffffu, t0, 2));
    t1 = add2(t1, __shfl_xor_sync(0xffffffffu, t1, 1));
    t1 = add2(t1, __shfl_xor_sync(0xffffffffu, t1, 2));

    float ps = 0.f, pq = 0.f;
    if (tig == 0) {
        float2 s0 = unpack2(t0), s1 = unpack2(t1);
        size_t base = blockRow + 32 * wid + gid;
        g_s[base]      = s0.x;
        g_s[base + 8]  = s0.y;
        g_s[base + 16] = s1.x;
        g_s[base + 24] = s1.y;
        ps = s0.x + s0.y + s1.x + s1.y;
        pq = s0.x * s0.x + s0.y * s0.y + s1.x * s1.x + s1.y * s1.y;
    }
    #pragma unroll
    for (int o = 16; o; o >>= 1) {
        ps += __shfl_xor_sync(0xffffffffu, ps, o);
        pq += __shfl_xor_sync(0xffffffffu, pq, o);
    }
    if (lane == 0) { redS[wid] = ps; redQ[wid] = pq; }
    __syncthreads();
    if (tid == 0) {
        float S = 0.f, Q = 0.f;
        #pragma unroll
        for (int i = 0; i < 8; i++) { S += redS[i]; Q += redQ[i]; }
        atomicAdd(&g_s3[0], S);
        atomicAdd(&g_s3[1], Q);
    }
}

// ---------------- K6: finalize BN3 affine ----------------------------------
__global__ void k_fin3(const float* __restrict__ g3, const float* __restrict__ b3) {
    float inv = 1.f / (float)MROWS;
    float mu  = g_s3[0] * inv;
    float var = g_s3[1] * inv - mu * mu;
    float rs  = rsqrtf(var + EPSV);
    float c   = g3[0] * rs;
    g_eaff[0] = c;
    g_eaff[1] = b3[0] - mu * c;
}

// ---------------- K7: masked row softmax ------------------------------------
__global__ void k_softmax(const float* __restrict__ adj_mean, float* __restrict__ out) {
    __shared__ float redm[8], reds[8];
    int row = blockIdx.x, tid = threadIdx.x, lane = tid & 31, w = tid >> 5;
    float c3 = g_eaff[0], d3 = g_eaff[1];
    float4 sv = ((const float4*)(g_s + (size_t)row * NROW))[tid];
    float4 mv = ((const float4*)(adj_mean + (size_t)row * NROW))[tid];
    float v0 = (mv.x > 0.f) ? leakyf(sv.x * c3 + d3) : NEGV;
    float v1 = (mv.y > 0.f) ? leakyf(sv.y * c3 + d3) : NEGV;
    float v2 = (mv.z > 0.f) ? leakyf(sv.z * c3 + d3) : NEGV;
    float v3 = (mv.w > 0.f) ? leakyf(sv.w * c3 + d3) : NEGV;

    float m = fmaxf(fmaxf(v0, v1), fmaxf(v2, v3));
    #pragma unroll
    for (int o = 16; o; o >>= 1) m = fmaxf(m, __shfl_xor_sync(0xffffffffu, m, o));
    if (lane == 0) redm[w] = m;
    __syncthreads();
    if (tid < 8) {
        float t = redm[tid];
        #pragma unroll
        for (int o = 4; o; o >>= 1) t = fmaxf(t, __shfl_xor_sync(0xffu, t, o));
        if (tid == 0) redm[0] = t;
    }
    __syncthreads();
    float rm = redm[0];

    float p0 = expf(v0 - rm), p1 = expf(v1 - rm), p2 = expf(v2 - rm), p3 = expf(v3 - rm);
    float s = p0 + p1 + p2 + p3;
    #pragma unroll
    for (int o = 16; o; o >>= 1) s += __shfl_xor_sync(0xffffffffu, s, o);
    if (lane == 0) reds[w] = s;
    __syncthreads();
    if (tid < 8) {
        float t = reds[tid];
        #pragma unroll
        for (int o = 4; o; o >>= 1) t += __shfl_xor_sync(0xffu, t, o);
        if (tid == 0) reds[0] = t;
    }
    __syncthreads();
    float invs = 1.f / reds[0];

    ((float4*)(out + (size_t)row * NROW))[tid] =
        make_float4(p0 * invs, p1 * invs, p2 * invs, p3 * invs);
}

// ---------------- launcher ---------------------------------------------------
extern "C" void kernel_launch(void* const* d_in, const int* in_sizes, int n_in,
                              void* d_out, int out_size) {
    const float* adj      = (const float*)d_in[0];
    const float* adj_mean = (const float*)d_in[1];
    const float* W        = (const float*)d_in[2];
    const float* a        = (const float*)d_in[3];
    const float* gamma1   = (const float*)d_in[4];
    const float* beta1    = (const float*)d_in[5];
    const float* gamma2   = (const float*)d_in[6];
    const float* beta2    = (const float*)d_in[7];
    const float* gamma3   = (const float*)d_in[8];
    const float* beta3    = (const float*)d_in[9];
    float* out            = (float*)d_out;

    k_zero<<<1, 256>>>();
    k_statsgram<<<GR_CTAS, 256>>>((const float4*)adj);
    k_gred<<<128, 256>>>();
    k_fin1<<<1, 128>>>(W, gamma1, beta1);
    k_fin2g<<<FHID, 128>>>(gamma2, beta2);
    k_gemm_fused<<<MROWS / GTM, 256>>>(adj, a);
    k_fin3<<<1, 1>>>(gamma3, beta3);
    k_softmax<<<NROW, 256>>>(adj_mean, out);
}